// round 5
// baseline (speedup 1.0000x reference)
#include <cuda_runtime.h>
#include <cstdint>

#define BATCH 512
#define TLEN  8192
#define DTC   1e-3f
#define TILE  512              // steps per tile
#define NTILE (TLEN / TILE)    // 16
#define NWARP 8                // warps per block
#define NTHR  (NWARP * 32)     // 256
#define LS    2                // steps per lane

// padded smem index: row = 8 steps + 1 pad slot
__device__ __forceinline__ int sidx(int s) { return (s >> 3) * 9 + (s & 7); }
#define ROWS      (TILE / 8)            // 64
#define SQ_ELEMS  (ROWS * 9)            // 576 float4
#define SD_ELEMS  (ROWS * 9)            // 576 float2
#define SQ_BYTES  (SQ_ELEMS * 16)       // 9216
#define SD_BYTES  (SD_ELEMS * 8)        // 4608
#define BUF_BYTES (SQ_BYTES + SD_BYTES) // 13824
#define SMEM_BYTES (2 * BUF_BYTES)      // 27648 (< 48KB default)

__device__ __forceinline__ void cp16(uint32_t dst, const void* src) {
    asm volatile("cp.async.cg.shared.global [%0], [%1], 16;" :: "r"(dst), "l"(src));
}
__device__ __forceinline__ void cp8(uint32_t dst, const void* src) {
    asm volatile("cp.async.ca.shared.global [%0], [%1], 8;" :: "r"(dst), "l"(src));
}
__device__ __forceinline__ void cp_commit() {
    asm volatile("cp.async.commit_group;");
}
template <int N>
__device__ __forceinline__ void cp_wait() {
    asm volatile("cp.async.wait_group %0;" :: "n"(N));
}

__device__ __forceinline__ void compose(float& M00, float& M01, float& M10, float& M11,
                                        float& v0, float& v1,
                                        float pM00, float pM01, float pM10, float pM11,
                                        float pv0, float pv1) {
    float n00 = M00 * pM00 + M01 * pM10;
    float n01 = M00 * pM01 + M01 * pM11;
    float n10 = M10 * pM00 + M11 * pM10;
    float n11 = M10 * pM01 + M11 * pM11;
    float nv0 = M00 * pv0 + M01 * pv1 + v0;
    float nv1 = M10 * pv0 + M11 * pv1 + v1;
    M00 = n00; M01 = n01; M10 = n10; M11 = n11; v0 = nv0; v1 = nv1;
}

__device__ __forceinline__ void warp_inclusive_scan(float& M00, float& M01, float& M10, float& M11,
                                                    float& v0, float& v1, int lane) {
    #pragma unroll
    for (int d = 1; d < 32; d <<= 1) {
        float pM00 = __shfl_up_sync(0xffffffffu, M00, d);
        float pM01 = __shfl_up_sync(0xffffffffu, M01, d);
        float pM10 = __shfl_up_sync(0xffffffffu, M10, d);
        float pM11 = __shfl_up_sync(0xffffffffu, M11, d);
        float pv0  = __shfl_up_sync(0xffffffffu, v0,  d);
        float pv1  = __shfl_up_sync(0xffffffffu, v1,  d);
        if (lane >= d) compose(M00, M01, M10, M11, v0, v1, pM00, pM01, pM10, pM11, pv0, pv1);
    }
}

__device__ __forceinline__ void step_transform(float4 q, float2 d,
                                               float a00, float a01, float a10, float a11,
                                               float c00, float c01, float c10, float c11,
                                               float& T00, float& T01, float& T10, float& T11,
                                               float& b0, float& b1) {
    T00 = 1.0f + DTC * (a00 - (q.x * c00 + q.y * c10));
    T01 =        DTC * (a01 - (q.x * c01 + q.y * c11));
    T10 =        DTC * (a10 - (q.z * c00 + q.w * c10));
    T11 = 1.0f + DTC * (a11 - (q.z * c01 + q.w * c11));
    b0  = q.x * d.x + q.y * d.y;
    b1  = q.z * d.x + q.w * d.y;
}

// ---------------- Fused pipelined kernel: one block per batch row ----------------
__global__ __launch_bounds__(NTHR, 4)
void kFused(const float4* __restrict__ xic, const float2* __restrict__ dyv,
            const float* __restrict__ Ac, const float* __restrict__ Cm,
            float2* __restrict__ out) {
    __shared__ char smem[SMEM_BYTES];
    __shared__ float wc[NWARP][6];   // warp composites
    __shared__ float xs[NWARP][2];   // state at start of each warp's segment
    __shared__ float carry[2];       // state carried across tiles

    const int tid  = threadIdx.x;
    const int lane = tid & 31;
    const int w    = tid >> 5;
    const int b    = blockIdx.x;

    const float c00 = __ldg(Cm + 0), c01 = __ldg(Cm + 1), c10 = __ldg(Cm + 2), c11 = __ldg(Cm + 3);
    const float a00 = __ldg(Ac + 0), a01 = __ldg(Ac + 1), a10 = __ldg(Ac + 2), a11 = __ldg(Ac + 3);

    if (tid == 0) { carry[0] = 1.0f; carry[1] = 0.0f; }

    const size_t rowbase = (size_t)b * TLEN;
    const uint32_t smem_u32 = (uint32_t)__cvta_generic_to_shared(smem);

    // stage tile `t` into buffer `buf` via cp.async (per-thread slots s = j*NTHR+tid)
    auto stage = [&](int t, int buf) {
        const uint32_t sq_u = smem_u32 + buf * BUF_BYTES;
        const uint32_t sd_u = sq_u + SQ_BYTES;
        const float4* xp = xic + rowbase + t * TILE;
        const float2* dp = dyv + rowbase + t * TILE;
        #pragma unroll
        for (int j = 0; j < TILE / NTHR; j++) {
            int s = j * NTHR + tid;
            int si = sidx(s);
            cp16(sq_u + si * 16, xp + s);
            cp8(sd_u + si * 8, dp + s);
        }
        cp_commit();
    };

    stage(0, 0);

    for (int tile = 0; tile < NTILE; tile++) {
        const int buf = tile & 1;
        const float4* sq = (const float4*)(smem + buf * BUF_BYTES);
        const float2* sd = (const float2*)(smem + buf * BUF_BYTES + SQ_BYTES);

        cp_wait<0>();
        __syncthreads();   // sync1: staged data visible to all

        // --- per-lane composite of 2 consecutive steps; keep q,d in regs ---
        const int s0 = w * (32 * LS) + lane * LS;
        float4 q0 = sq[sidx(s0 + 0)];
        float4 q1 = sq[sidx(s0 + 1)];
        float2 d0 = sd[sidx(s0 + 0)];
        float2 d1 = sd[sidx(s0 + 1)];

        float M00, M01, M10, M11, v0, v1;        // step-0 transform
        step_transform(q0, d0, a00, a01, a10, a11, c00, c01, c10, c11, M00, M01, M10, M11, v0, v1);
        {
            float T00, T01, T10, T11, b0, b1;    // step-1 transform, composed on top
            step_transform(q1, d1, a00, a01, a10, a11, c00, c01, c10, c11, T00, T01, T10, T11, b0, b1);
            float n00 = T00 * M00 + T01 * M10;
            float n01 = T00 * M01 + T01 * M11;
            float n10 = T10 * M00 + T11 * M10;
            float n11 = T10 * M01 + T11 * M11;
            float nv0 = T00 * v0 + T01 * v1 + b0;
            float nv1 = T10 * v0 + T11 * v1 + b1;
            M00 = n00; M01 = n01; M10 = n10; M11 = n11; v0 = nv0; v1 = nv1;
        }

        warp_inclusive_scan(M00, M01, M10, M11, v0, v1, lane);

        if (lane == 31) {
            wc[w][0] = M00; wc[w][1] = M01; wc[w][2] = M10;
            wc[w][3] = M11; wc[w][4] = v0;  wc[w][5] = v1;
        }
        __syncthreads();   // sync2: wc ready; also: all compose-reads of buf done

        // prefetch next tile (overlaps chain + replay + next wait)
        if (tile + 1 < NTILE) stage(tile + 1, buf ^ 1);

        // --- serial chain of warp composites through the carry (thread 0) ---
        if (tid == 0) {
            float x0 = carry[0], x1 = carry[1];
            #pragma unroll
            for (int i = 0; i < NWARP; i++) {
                xs[i][0] = x0; xs[i][1] = x1;
                float nx0 = wc[i][0] * x0 + wc[i][1] * x1 + wc[i][4];
                float nx1 = wc[i][2] * x0 + wc[i][3] * x1 + wc[i][5];
                x0 = nx0; x1 = nx1;
            }
            carry[0] = x0; carry[1] = x1;
        }
        __syncthreads();   // sync3: xs ready

        // --- exclusive lane prefix, then replay from registers ---
        float pM00 = __shfl_up_sync(0xffffffffu, M00, 1);
        float pM01 = __shfl_up_sync(0xffffffffu, M01, 1);
        float pM10 = __shfl_up_sync(0xffffffffu, M10, 1);
        float pM11 = __shfl_up_sync(0xffffffffu, M11, 1);
        float pv0  = __shfl_up_sync(0xffffffffu, v0,  1);
        float pv1  = __shfl_up_sync(0xffffffffu, v1,  1);
        if (lane == 0) { pM00 = 1.f; pM01 = 0.f; pM10 = 0.f; pM11 = 1.f; pv0 = 0.f; pv1 = 0.f; }

        float xw0 = xs[w][0], xw1 = xs[w][1];
        float x0 = pM00 * xw0 + pM01 * xw1 + pv0;
        float x1 = pM10 * xw0 + pM11 * xw1 + pv1;

        float2* op = out + rowbase + tile * TILE + s0;

        // step 0
        float2 o0;
        o0.x = DTC * (c00 * x0 + c01 * x1);
        o0.y = DTC * (c10 * x0 + c11 * x1);
        op[0] = o0;
        {
            float T00, T01, T10, T11, b0, b1;
            step_transform(q0, d0, a00, a01, a10, a11, c00, c01, c10, c11, T00, T01, T10, T11, b0, b1);
            float nx0 = T00 * x0 + T01 * x1 + b0;
            float nx1 = T10 * x0 + T11 * x1 + b1;
            x0 = nx0; x1 = nx1;
        }
        // step 1
        float2 o1;
        o1.x = DTC * (c00 * x0 + c01 * x1);
        o1.y = DTC * (c10 * x0 + c11 * x1);
        op[1] = o1;
        // no trailing sync: replay touched no smem; buf's next writer is
        // stage(tile+2) which sits behind sync2(tile+1).
    }
}

extern "C" void kernel_launch(void* const* d_in, const int* in_sizes, int n_in,
                              void* d_out, int out_size) {
    const float4* xic = (const float4*)d_in[0];   // [B,T,2,2] f32
    const float2* dyv = (const float2*)d_in[1];   // [B,T,2]   f32
    const float*  Ac  = (const float*)d_in[2];    // [2,2]
    const float*  Cm  = (const float*)d_in[3];    // [2,2]
    float2* out = (float2*)d_out;                 // [B,T,2]

    kFused<<<BATCH, NTHR>>>(xic, dyv, Ac, Cm, out);
}